// round 1
// baseline (speedup 1.0000x reference)
#include <cuda_runtime.h>
#include <cuda_bf16.h>

#define NH 32
#define TDIM 1024
#define SDIM 1024
#define DDIM 128
#define TS (TDIM * SDIM)

// Scratch: logits / probs buffers, [N, T, S] each. Static device globals (no runtime alloc).
__device__ float g_A[(size_t)NH * TS];
__device__ float g_B[(size_t)NH * TS];

// ---------------------------------------------------------------------------
// K1: logits[n,t,s] = sum_d Q[n,t,d] * K[n,s,d]   (causal tiles only)
// 64x64 output tile per block, k-chunks of 32.
// ---------------------------------------------------------------------------
__global__ __launch_bounds__(256) void qk_gemm(const float* __restrict__ Q,
                                               const float* __restrict__ K) {
    int bx = blockIdx.x;  // s tile
    int by = blockIdx.y;  // t tile
    int n  = blockIdx.z;
    if (bx > by) return;  // fully above causal diagonal

    __shared__ float Qs[64][33];
    __shared__ float Ks[64][33];
    int tx = threadIdx.x & 15;
    int ty = threadIdx.x >> 4;

    const float* Qn = Q + ((size_t)n * TDIM + by * 64) * DDIM;
    const float* Kn = K + ((size_t)n * SDIM + bx * 64) * DDIM;

    float acc[4][4] = {};
    for (int k0 = 0; k0 < DDIM; k0 += 32) {
        for (int l = threadIdx.x; l < 64 * 32; l += 256) {
            int r = l >> 5, c = l & 31;
            Qs[r][c] = Qn[r * DDIM + k0 + c];
            Ks[r][c] = Kn[r * DDIM + k0 + c];
        }
        __syncthreads();
#pragma unroll
        for (int kk = 0; kk < 32; kk++) {
            float a[4], b[4];
#pragma unroll
            for (int i = 0; i < 4; i++) a[i] = Qs[i * 16 + ty][kk];
#pragma unroll
            for (int j = 0; j < 4; j++) b[j] = Ks[j * 16 + tx][kk];
#pragma unroll
            for (int i = 0; i < 4; i++)
#pragma unroll
                for (int j = 0; j < 4; j++) acc[i][j] += a[i] * b[j];
        }
        __syncthreads();
    }
    float* Cn = g_A + (size_t)n * TS;
#pragma unroll
    for (int i = 0; i < 4; i++) {
        int t = by * 64 + i * 16 + ty;
#pragma unroll
        for (int j = 0; j < 4; j++) {
            int s = bx * 64 + j * 16 + tx;
            Cn[(size_t)t * SDIM + s] = acc[i][j];
        }
    }
}

// ---------------------------------------------------------------------------
// K2/K4: cross-head projection, pointwise in (t,s).
//   out[m] = x[m] + sum_n x[n]*sw[n,m]
//          + sum_i (sum_n x[n]*qw1[t,i,n]) * qw2[t,i,m]
//          + sum_i (sum_n x[n]*kw1[s,i,n]) * kw2[s,i,m]
//          + x[m]*(qdd[t,m] + kdd[s,m])
// pre (post=0): read g_A, write g_B, skip s>t.
// post (post=1): read g_B, write g_A, zero-fill s>t (so AV GEMM reads zeros).
// ---------------------------------------------------------------------------
__global__ __launch_bounds__(256) void proj_kernel(
    int post,
    const float* __restrict__ sw,
    const float* __restrict__ qw1, const float* __restrict__ qw2,
    const float* __restrict__ kw1, const float* __restrict__ kw2,
    const float* __restrict__ qdd, const float* __restrict__ kdd) {
    __shared__ float sws[32 * 32];
    __shared__ float qw1s[64], qw2s[64], qdds[32];

    int t = blockIdx.y;
    int s = blockIdx.x * 256 + threadIdx.x;

    for (int l = threadIdx.x; l < 1024; l += 256) sws[l] = sw[l];
    if (threadIdx.x < 64)       qw1s[threadIdx.x]       = qw1[t * 64 + threadIdx.x];
    else if (threadIdx.x < 128) qw2s[threadIdx.x - 64]  = qw2[t * 64 + (threadIdx.x - 64)];
    else if (threadIdx.x < 160) qdds[threadIdx.x - 128] = qdd[t * 32 + (threadIdx.x - 128)];
    __syncthreads();

    const float* src = post ? g_B : g_A;
    float*       dst = post ? g_A : g_B;

    if (s > t) {
        if (post) {
#pragma unroll 4
            for (int m = 0; m < 32; m++) dst[(size_t)m * TS + (size_t)t * SDIM + s] = 0.0f;
        }
        return;
    }

    float x[32];
#pragma unroll
    for (int n = 0; n < 32; n++) x[n] = src[(size_t)n * TS + (size_t)t * SDIM + s];

    const float* kw1r = kw1 + (size_t)s * 64;
    float qh0 = 0.f, qh1 = 0.f, kh0 = 0.f, kh1 = 0.f;
#pragma unroll
    for (int n = 0; n < 32; n++) {
        qh0 += x[n] * qw1s[n];
        qh1 += x[n] * qw1s[32 + n];
        kh0 += x[n] * kw1r[n];
        kh1 += x[n] * kw1r[32 + n];
    }

    const float* kw2r = kw2 + (size_t)s * 64;
    const float* kddr = kdd + (size_t)s * 32;
#pragma unroll 4
    for (int m = 0; m < 32; m++) {
        float acc = x[m];
#pragma unroll
        for (int n = 0; n < 32; n++) acc += x[n] * sws[n * 32 + m];
        acc += qh0 * qw2s[m] + qh1 * qw2s[32 + m];
        acc += kh0 * kw2r[m] + kh1 * kw2r[32 + m];
        acc += x[m] * (qdds[m] + kddr[m]);
        dst[(size_t)m * TS + (size_t)t * SDIM + s] = acc;
    }
}

// ---------------------------------------------------------------------------
// K3: row softmax over s in [0, t] (masked region never read; probs there
// are exactly 0 in the reference since mask = finfo.min*0.5).
// ---------------------------------------------------------------------------
__global__ __launch_bounds__(256) void softmax_kernel() {
    int t = blockIdx.x;
    int n = blockIdx.y;
    float* row = g_B + (size_t)n * TS + (size_t)t * SDIM;
    int len = t + 1;
    __shared__ float red[8];
    int tid = threadIdx.x;
    int lane = tid & 31, wid = tid >> 5;

    float lmax = -3.4e38f;
    for (int s = tid; s < len; s += 256) lmax = fmaxf(lmax, row[s]);
#pragma unroll
    for (int o = 16; o; o >>= 1) lmax = fmaxf(lmax, __shfl_xor_sync(~0u, lmax, o));
    if (lane == 0) red[wid] = lmax;
    __syncthreads();
    if (tid == 0) {
        float v = red[0];
#pragma unroll
        for (int w = 1; w < 8; w++) v = fmaxf(v, red[w]);
        red[0] = v;
    }
    __syncthreads();
    float bmax = red[0];
    __syncthreads();

    float lsum = 0.f;
    for (int s = tid; s < len; s += 256) lsum += __expf(row[s] - bmax);
#pragma unroll
    for (int o = 16; o; o >>= 1) lsum += __shfl_xor_sync(~0u, lsum, o);
    if (lane == 0) red[wid] = lsum;
    __syncthreads();
    if (tid == 0) {
        float v = 0.f;
#pragma unroll
        for (int w = 0; w < 8; w++) v += red[w];
        red[0] = v;
    }
    __syncthreads();
    float inv = 1.0f / red[0];

    for (int s = tid; s < len; s += 256) row[s] = __expf(row[s] - bmax) * inv;
}

// ---------------------------------------------------------------------------
// K5: out[n,t,d] = sum_s P[n,t,s] * V[n,s,d]
// Block: 64 t-rows x 128 d (full). s chunks of 32, causal upper bound.
// P above diagonal was zero-filled by post proj -> safe full-tile reads.
// ---------------------------------------------------------------------------
__global__ __launch_bounds__(256) void av_gemm(const float* __restrict__ V,
                                               float* __restrict__ out) {
    int tb = blockIdx.x;  // t tile
    int n  = blockIdx.y;

    __shared__ float Ps[64][33];
    __shared__ float Vs[32][128];

    int tx = threadIdx.x & 15;
    int ty = threadIdx.x >> 4;

    const float* Pn = g_A + (size_t)n * TS + (size_t)tb * 64 * SDIM;
    const float* Vn = V + (size_t)n * SDIM * DDIM;

    float acc[4][8] = {};
    int nchunks = (tb + 1) * 2;  // cover s <= tb*64+63
    for (int c = 0; c < nchunks; c++) {
        int s0 = c * 32;
        for (int l = threadIdx.x; l < 64 * 32; l += 256) {
            int r = l >> 5, cc = l & 31;
            Ps[r][cc] = Pn[(size_t)r * SDIM + s0 + cc];
        }
        for (int l = threadIdx.x; l < 32 * 128; l += 256) {
            int r = l >> 7, cc = l & 127;
            Vs[r][cc] = Vn[(size_t)(s0 + r) * DDIM + cc];
        }
        __syncthreads();
#pragma unroll
        for (int ss = 0; ss < 32; ss++) {
            float p[4], v[8];
#pragma unroll
            for (int i = 0; i < 4; i++) p[i] = Ps[i * 16 + ty][ss];
#pragma unroll
            for (int j = 0; j < 8; j++) v[j] = Vs[ss][j * 16 + tx];
#pragma unroll
            for (int i = 0; i < 4; i++)
#pragma unroll
                for (int j = 0; j < 8; j++) acc[i][j] += p[i] * v[j];
        }
        __syncthreads();
    }

#pragma unroll
    for (int i = 0; i < 4; i++) {
        int t = tb * 64 + i * 16 + ty;
#pragma unroll
        for (int j = 0; j < 8; j++) {
            out[((size_t)n * TDIM + t) * DDIM + j * 16 + tx] = acc[i][j];
        }
    }
}

// ---------------------------------------------------------------------------
// Launch
// ---------------------------------------------------------------------------
extern "C" void kernel_launch(void* const* d_in, const int* in_sizes, int n_in,
                              void* d_out, int out_size) {
    const float* query = (const float*)d_in[0];   // [1,32,1024,128]
    const float* key   = (const float*)d_in[1];   // [1,32,1024,128]
    const float* value = (const float*)d_in[2];   // [1,32,1024,128]
    // d_in[3] = atten_mask (causal; handled structurally)
    const float* sw_pre  = (const float*)d_in[4];
    const float* qw1_pre = (const float*)d_in[5];
    const float* qw2_pre = (const float*)d_in[6];
    const float* kw1_pre = (const float*)d_in[7];
    const float* kw2_pre = (const float*)d_in[8];
    const float* qdd_pre = (const float*)d_in[9];
    const float* kdd_pre = (const float*)d_in[10];
    const float* sw_post  = (const float*)d_in[11];
    const float* qw1_post = (const float*)d_in[12];
    const float* qw2_post = (const float*)d_in[13];
    const float* kw1_post = (const float*)d_in[14];
    const float* kw2_post = (const float*)d_in[15];
    const float* qdd_post = (const float*)d_in[16];
    const float* kdd_post = (const float*)d_in[17];
    float* out = (float*)d_out;                   // [1,32,1024,128]

    qk_gemm<<<dim3(16, 16, 32), 256>>>(query, key);
    proj_kernel<<<dim3(4, 1024), 256>>>(0, sw_pre, qw1_pre, qw2_pre,
                                        kw1_pre, kw2_pre, qdd_pre, kdd_pre);
    softmax_kernel<<<dim3(1024, 32), 256>>>();
    proj_kernel<<<dim3(4, 1024), 256>>>(1, sw_post, qw1_post, qw2_post,
                                        kw1_post, kw2_post, qdd_post, kdd_post);
    av_gemm<<<dim3(16, 32), 256>>>(value, out);
}

// round 2
// speedup vs baseline: 1.7830x; 1.7830x over previous
#include <cuda_runtime.h>
#include <cuda_bf16.h>
#include <math_constants.h>

#define NH 32
#define TDIM 1024
#define SDIM 1024
#define DDIM 128
#define TS (TDIM * SDIM)

// Scratch buffers [N, T, S]. Static device globals (no runtime alloc).
__device__ float g_A[(size_t)NH * TS];   // raw logits (QK output)
__device__ float g_B[(size_t)NH * TS];   // final probs (AV input)

// ---------------------------------------------------------------------------
// K1: logits[n,t,s] = sum_d Q[n,t,d] * K[n,s,d]   (causal tiles only)
// ---------------------------------------------------------------------------
__global__ __launch_bounds__(256) void qk_gemm(const float* __restrict__ Q,
                                               const float* __restrict__ K) {
    int bx = blockIdx.x;  // s tile
    int by = blockIdx.y;  // t tile
    int n  = blockIdx.z;
    if (bx > by) return;

    __shared__ float Qs[64][33];
    __shared__ float Ks[64][33];
    int tx = threadIdx.x & 15;
    int ty = threadIdx.x >> 4;

    const float* Qn = Q + ((size_t)n * TDIM + by * 64) * DDIM;
    const float* Kn = K + ((size_t)n * SDIM + bx * 64) * DDIM;

    float acc[4][4] = {};
    for (int k0 = 0; k0 < DDIM; k0 += 32) {
        for (int l = threadIdx.x; l < 64 * 32; l += 256) {
            int r = l >> 5, c = l & 31;
            Qs[r][c] = Qn[r * DDIM + k0 + c];
            Ks[r][c] = Kn[r * DDIM + k0 + c];
        }
        __syncthreads();
#pragma unroll
        for (int kk = 0; kk < 32; kk++) {
            float a[4], b[4];
#pragma unroll
            for (int i = 0; i < 4; i++) a[i] = Qs[i * 16 + ty][kk];
#pragma unroll
            for (int j = 0; j < 4; j++) b[j] = Ks[j * 16 + tx][kk];
#pragma unroll
            for (int i = 0; i < 4; i++)
#pragma unroll
                for (int j = 0; j < 4; j++) acc[i][j] += a[i] * b[j];
        }
        __syncthreads();
    }
    float* Cn = g_A + (size_t)n * TS;
#pragma unroll
    for (int i = 0; i < 4; i++) {
        int t = by * 64 + i * 16 + ty;
#pragma unroll
        for (int j = 0; j < 4; j++) {
            int s = bx * 64 + j * 16 + tx;
            Cn[(size_t)t * SDIM + s] = acc[i][j];
        }
    }
}

// ---------------------------------------------------------------------------
// Cross-head projection of one point (x[32] in regs -> out[32]).
// out[m] = x[m]*(1 + qdd[m] + kdd[m]) + sum_n x[n]*sw[n][m]
//        + sum_i qh_i*qw2[i][m] + sum_i kh_i*kw2[i][m]
// kw1v/kw2v/kddv are gmem float4 pointers already offset to row s.
// ---------------------------------------------------------------------------
__device__ __forceinline__ void chp_point(
    const float* __restrict__ x,
    const float* __restrict__ sws,   // smem [32][32]
    const float* __restrict__ qw1s,  // smem [2][32]
    const float* __restrict__ qw2s,  // smem [2][32]
    const float* __restrict__ qdds,  // smem [32]
    const float4* __restrict__ kw1v, // gmem, row s
    const float4* __restrict__ kw2v, // gmem, row s
    const float4* __restrict__ kddv, // gmem, row s
    float* __restrict__ out) {
    float qh0 = 0.f, qh1 = 0.f, kh0 = 0.f, kh1 = 0.f;
    const float4* qw1v = (const float4*)qw1s;
#pragma unroll
    for (int j = 0; j < 8; j++) {
        float4 a = qw1v[j];
        float4 b = qw1v[8 + j];
        float4 c = kw1v[j];
        float4 d = kw1v[8 + j];
        float x0 = x[4 * j], x1 = x[4 * j + 1], x2 = x[4 * j + 2], x3 = x[4 * j + 3];
        qh0 += x0 * a.x + x1 * a.y + x2 * a.z + x3 * a.w;
        qh1 += x0 * b.x + x1 * b.y + x2 * b.z + x3 * b.w;
        kh0 += x0 * c.x + x1 * c.y + x2 * c.z + x3 * c.w;
        kh1 += x0 * d.x + x1 * d.y + x2 * d.z + x3 * d.w;
    }
    const float4* qw2v = (const float4*)qw2s;
    const float4* qddv = (const float4*)qdds;
    const float4* swv  = (const float4*)sws;
#pragma unroll
    for (int mc = 0; mc < 8; mc++) {
        float4 q2a = qw2v[mc];
        float4 q2b = qw2v[8 + mc];
        float4 k2a = kw2v[mc];
        float4 k2b = kw2v[8 + mc];
        float4 kd  = kddv[mc];
        float4 qd  = qddv[mc];
        int m0 = mc * 4;
        float a0 = x[m0 + 0] * (1.f + qd.x + kd.x) + qh0 * q2a.x + qh1 * q2b.x + kh0 * k2a.x + kh1 * k2b.x;
        float a1 = x[m0 + 1] * (1.f + qd.y + kd.y) + qh0 * q2a.y + qh1 * q2b.y + kh0 * k2a.y + kh1 * k2b.y;
        float a2 = x[m0 + 2] * (1.f + qd.z + kd.z) + qh0 * q2a.z + qh1 * q2b.z + kh0 * k2a.z + kh1 * k2b.z;
        float a3 = x[m0 + 3] * (1.f + qd.w + kd.w) + qh0 * q2a.w + qh1 * q2b.w + kh0 * k2a.w + kh1 * k2b.w;
#pragma unroll
        for (int n = 0; n < 32; n++) {
            float4 w = swv[n * 8 + mc];
            float xn = x[n];
            a0 += xn * w.x;
            a1 += xn * w.y;
            a2 += xn * w.z;
            a3 += xn * w.w;
        }
        out[m0 + 0] = a0;
        out[m0 + 1] = a1;
        out[m0 + 2] = a2;
        out[m0 + 3] = a3;
    }
}

// ---------------------------------------------------------------------------
// K2 (fused middle): per t-row CTA:
//   pre-proj(g_A) -> smem row -> softmax -> post-proj -> g_B (+zero fill)
// smem row P: [32][1025] fp32 (pad avoids column bank conflicts).
// ---------------------------------------------------------------------------
#define PSTRIDE 1025
#define MID_THREADS 512
#define MID_SMEM_FLOATS (32 * PSTRIDE + 2048 + 256 + 64)
// layout: P[32*1025] | swp[1024] | swo[1024] | qw1p[64] qw2p[64] qw1o[64] qw2o[64] | qddp[32] qddo[32]

extern __shared__ float s_mid[];

__global__ __launch_bounds__(MID_THREADS, 1) void middle_kernel(
    const float* __restrict__ sw_pre,
    const float* __restrict__ qw1_pre, const float* __restrict__ qw2_pre,
    const float* __restrict__ kw1_pre, const float* __restrict__ kw2_pre,
    const float* __restrict__ qdd_pre, const float* __restrict__ kdd_pre,
    const float* __restrict__ sw_post,
    const float* __restrict__ qw1_post, const float* __restrict__ qw2_post,
    const float* __restrict__ kw1_post, const float* __restrict__ kw2_post,
    const float* __restrict__ qdd_post, const float* __restrict__ kdd_post) {
    int t = 1023 - blockIdx.x;  // longest rows first
    int len = t + 1;
    int pad = ((t >> 6) + 1) << 6;  // AV reads s < pad for this row's tile
    int tid = threadIdx.x;

    float* P    = s_mid;
    float* swp  = s_mid + 32 * PSTRIDE;
    float* swo  = swp + 1024;
    float* qw1p = swo + 1024;
    float* qw2p = qw1p + 64;
    float* qw1o = qw2p + 64;
    float* qw2o = qw1o + 64;
    float* qddp = qw2o + 64;
    float* qddo = qddp + 32;

    // stage weights
    for (int l = tid; l < 1024; l += MID_THREADS) {
        swp[l] = sw_pre[l];
        swo[l] = sw_post[l];
    }
    if (tid < 64) qw1p[tid] = qw1_pre[t * 64 + tid];
    else if (tid < 128) qw2p[tid - 64] = qw2_pre[t * 64 + tid - 64];
    else if (tid < 192) qw1o[tid - 128] = qw1_post[t * 64 + tid - 128];
    else if (tid < 256) qw2o[tid - 192] = qw2_post[t * 64 + tid - 192];
    else if (tid < 288) qddp[tid - 256] = qdd_pre[t * 32 + tid - 256];
    else if (tid < 320) qddo[tid - 288] = qdd_post[t * 32 + tid - 288];
    __syncthreads();

    // ---- phase 1: pre-projection g_A -> P ----
    for (int s = tid; s < len; s += MID_THREADS) {
        const float* xg = g_A + (size_t)t * SDIM + s;
        float x[32];
#pragma unroll
        for (int n = 0; n < 32; n++) x[n] = xg[(size_t)n * TS];
        float out[32];
        chp_point(x, swp, qw1p, qw2p, qddp,
                  (const float4*)(kw1_pre + (size_t)s * 64),
                  (const float4*)(kw2_pre + (size_t)s * 64),
                  (const float4*)(kdd_pre + (size_t)s * 32),
                  out);
#pragma unroll
        for (int m = 0; m < 32; m++) P[m * PSTRIDE + s] = out[m];
    }
    __syncthreads();

    // ---- phase 2: softmax per head (warp per head; 16 warps x 2 heads) ----
    int warp = tid >> 5, lane = tid & 31;
    for (int h = warp; h < 32; h += 16) {
        float* row = P + h * PSTRIDE;
        float mx = -CUDART_INF_F;
        for (int s = lane; s < len; s += 32) mx = fmaxf(mx, row[s]);
#pragma unroll
        for (int o = 16; o; o >>= 1) mx = fmaxf(mx, __shfl_xor_sync(~0u, mx, o));
        float Z = 0.f;
        for (int s = lane; s < len; s += 32) {
            float e = __expf(row[s] - mx);
            row[s] = e;
            Z += e;
        }
#pragma unroll
        for (int o = 16; o; o >>= 1) Z += __shfl_xor_sync(~0u, Z, o);
        float inv = 1.0f / Z;
        for (int s = lane; s < len; s += 32) row[s] *= inv;
    }
    __syncthreads();

    // ---- phase 3: post-projection P -> g_B (+ zero fill to pad) ----
    for (int s = tid; s < pad; s += MID_THREADS) {
        float* dst = g_B + (size_t)t * SDIM + s;
        if (s < len) {
            float x[32];
#pragma unroll
            for (int n = 0; n < 32; n++) x[n] = P[n * PSTRIDE + s];
            float out[32];
            chp_point(x, swo, qw1o, qw2o, qddo,
                      (const float4*)(kw1_post + (size_t)s * 64),
                      (const float4*)(kw2_post + (size_t)s * 64),
                      (const float4*)(kdd_post + (size_t)s * 32),
                      out);
#pragma unroll
            for (int m = 0; m < 32; m++) dst[(size_t)m * TS] = out[m];
        } else {
#pragma unroll
            for (int m = 0; m < 32; m++) dst[(size_t)m * TS] = 0.0f;
        }
    }
}

// ---------------------------------------------------------------------------
// K3: out[n,t,d] = sum_s P[n,t,s] * V[n,s,d]  (causal chunk bound; P zero-
// filled above diagonal up to 64-boundary)
// ---------------------------------------------------------------------------
__global__ __launch_bounds__(256) void av_gemm(const float* __restrict__ V,
                                               float* __restrict__ out) {
    int tb = blockIdx.x;
    int n  = blockIdx.y;

    __shared__ float Ps[64][33];
    __shared__ float Vs[32][128];

    int tx = threadIdx.x & 15;
    int ty = threadIdx.x >> 4;

    const float* Pn = g_B + (size_t)n * TS + (size_t)tb * 64 * SDIM;
    const float* Vn = V + (size_t)n * SDIM * DDIM;

    float acc[4][8] = {};
    int nchunks = (tb + 1) * 2;
    for (int c = 0; c < nchunks; c++) {
        int s0 = c * 32;
        for (int l = threadIdx.x; l < 64 * 32; l += 256) {
            int r = l >> 5, cc = l & 31;
            Ps[r][cc] = Pn[(size_t)r * SDIM + s0 + cc];
        }
        for (int l = threadIdx.x; l < 32 * 128; l += 256) {
            int r = l >> 7, cc = l & 127;
            Vs[r][cc] = Vn[(size_t)(s0 + r) * DDIM + cc];
        }
        __syncthreads();
#pragma unroll
        for (int ss = 0; ss < 32; ss++) {
            float p[4], v[8];
#pragma unroll
            for (int i = 0; i < 4; i++) p[i] = Ps[i * 16 + ty][ss];
#pragma unroll
            for (int j = 0; j < 8; j++) v[j] = Vs[ss][j * 16 + tx];
#pragma unroll
            for (int i = 0; i < 4; i++)
#pragma unroll
                for (int j = 0; j < 8; j++) acc[i][j] += p[i] * v[j];
        }
        __syncthreads();
    }

#pragma unroll
    for (int i = 0; i < 4; i++) {
        int t = tb * 64 + i * 16 + ty;
#pragma unroll
        for (int j = 0; j < 8; j++) {
            out[((size_t)n * TDIM + t) * DDIM + j * 16 + tx] = acc[i][j];
        }
    }
}

// ---------------------------------------------------------------------------
// Launch
// ---------------------------------------------------------------------------
extern "C" void kernel_launch(void* const* d_in, const int* in_sizes, int n_in,
                              void* d_out, int out_size) {
    const float* query = (const float*)d_in[0];
    const float* key   = (const float*)d_in[1];
    const float* value = (const float*)d_in[2];
    const float* sw_pre  = (const float*)d_in[4];
    const float* qw1_pre = (const float*)d_in[5];
    const float* qw2_pre = (const float*)d_in[6];
    const float* kw1_pre = (const float*)d_in[7];
    const float* kw2_pre = (const float*)d_in[8];
    const float* qdd_pre = (const float*)d_in[9];
    const float* kdd_pre = (const float*)d_in[10];
    const float* sw_post  = (const float*)d_in[11];
    const float* qw1_post = (const float*)d_in[12];
    const float* qw2_post = (const float*)d_in[13];
    const float* kw1_post = (const float*)d_in[14];
    const float* kw2_post = (const float*)d_in[15];
    const float* qdd_post = (const float*)d_in[16];
    const float* kdd_post = (const float*)d_in[17];
    float* out = (float*)d_out;

    size_t mid_smem = MID_SMEM_FLOATS * sizeof(float);
    cudaFuncSetAttribute(middle_kernel,
                         cudaFuncAttributeMaxDynamicSharedMemorySize,
                         (int)mid_smem);

    qk_gemm<<<dim3(16, 16, 32), 256>>>(query, key);
    middle_kernel<<<1024, MID_THREADS, mid_smem>>>(
        sw_pre, qw1_pre, qw2_pre, kw1_pre, kw2_pre, qdd_pre, kdd_pre,
        sw_post, qw1_post, qw2_post, kw1_post, kw2_post, qdd_post, kdd_post);
    av_gemm<<<dim3(16, 32), 256>>>(value, out);
}

// round 3
// speedup vs baseline: 3.0145x; 1.6907x over previous
#include <cuda_runtime.h>
#include <cuda_bf16.h>
#include <math_constants.h>
#include <cstdint>

#define NH 32
#define TDIM 1024
#define SDIM 1024
#define DDIM 128
#define TS (TDIM * SDIM)

// Scratch buffers [N, T, S]. Static device globals (no runtime alloc).
__device__ float g_A[(size_t)NH * TS];   // raw logits (QK output)
__device__ float g_B[(size_t)NH * TS];   // final probs (AV input)

// ---------------------------------------------------------------------------
// tf32 helpers
// ---------------------------------------------------------------------------
__device__ __forceinline__ uint32_t f2tf32(float f) {
    uint32_t u;
    asm("cvt.rna.tf32.f32 %0, %1;" : "=r"(u) : "f"(f));
    return u;
}

__device__ __forceinline__ void mma_tf32(float* c, const uint32_t* a, const uint32_t* b) {
    asm volatile(
        "mma.sync.aligned.m16n8k8.row.col.f32.tf32.tf32.f32 "
        "{%0,%1,%2,%3}, {%4,%5,%6,%7}, {%8,%9}, {%0,%1,%2,%3};"
        : "+f"(c[0]), "+f"(c[1]), "+f"(c[2]), "+f"(c[3])
        : "r"(a[0]), "r"(a[1]), "r"(a[2]), "r"(a[3]), "r"(b[0]), "r"(b[1]));
}

// ---------------------------------------------------------------------------
// K1: logits[n,t,s] = sum_d Q[n,t,d]*K[n,s,d], tf32 tensor cores.
// Block tile 128x128, warp tile 64x32 (4x4 mma tiles of 16x8), K chunks of 64.
// smem stride 68 (mod 32 == 4): fragment LDS conflict-free.
// ---------------------------------------------------------------------------
#define QK_STR 68
#define QK_SMEM_BYTES (2 * 128 * QK_STR * 4)

__global__ __launch_bounds__(256) void qk_gemm(const float* __restrict__ Q,
                                               const float* __restrict__ K) {
    int bx = blockIdx.x;  // s tile
    int by = blockIdx.y;  // t tile
    int n  = blockIdx.z;
    if (bx > by) return;

    extern __shared__ uint32_t sm_qk[];
    uint32_t* Qs = sm_qk;                 // [128][68]
    uint32_t* Ks = sm_qk + 128 * QK_STR;  // [128][68]

    const float* Qn = Q + ((size_t)n * TDIM + by * 128) * DDIM;
    const float* Kn = K + ((size_t)n * SDIM + bx * 128) * DDIM;

    int tid = threadIdx.x;
    int lane = tid & 31, warp = tid >> 5;
    int wm = warp >> 2, wn = warp & 3;
    int g = lane >> 2, tg = lane & 3;

    float acc[4][4][4] = {};

    for (int k0 = 0; k0 < DDIM; k0 += 64) {
        // stage 128x64 of Q and K (cvt to tf32)
#pragma unroll
        for (int i = 0; i < 8; i++) {
            int idx = tid + i * 256;      // 2048 float4 per tile
            int r = idx >> 4, c4 = idx & 15;
            float4 q = *(const float4*)(Qn + (size_t)r * DDIM + k0 + c4 * 4);
            float4 k = *(const float4*)(Kn + (size_t)r * DDIM + k0 + c4 * 4);
            uint32_t* qd = Qs + r * QK_STR + c4 * 4;
            uint32_t* kd = Ks + r * QK_STR + c4 * 4;
            qd[0] = f2tf32(q.x); qd[1] = f2tf32(q.y); qd[2] = f2tf32(q.z); qd[3] = f2tf32(q.w);
            kd[0] = f2tf32(k.x); kd[1] = f2tf32(k.y); kd[2] = f2tf32(k.z); kd[3] = f2tf32(k.w);
        }
        __syncthreads();

#pragma unroll
        for (int ks = 0; ks < 64; ks += 8) {
            uint32_t a[4][4], b[4][2];
#pragma unroll
            for (int mi = 0; mi < 4; mi++) {
                int rb = wm * 64 + mi * 16;
                a[mi][0] = Qs[(rb + g) * QK_STR + ks + tg];
                a[mi][1] = Qs[(rb + g + 8) * QK_STR + ks + tg];
                a[mi][2] = Qs[(rb + g) * QK_STR + ks + tg + 4];
                a[mi][3] = Qs[(rb + g + 8) * QK_STR + ks + tg + 4];
            }
#pragma unroll
            for (int ni = 0; ni < 4; ni++) {
                int nb = wn * 32 + ni * 8;
                b[ni][0] = Ks[(nb + g) * QK_STR + ks + tg];
                b[ni][1] = Ks[(nb + g) * QK_STR + ks + tg + 4];
            }
#pragma unroll
            for (int mi = 0; mi < 4; mi++)
#pragma unroll
                for (int ni = 0; ni < 4; ni++) mma_tf32(acc[mi][ni], a[mi], b[ni]);
        }
        __syncthreads();
    }

    float* Cn = g_A + (size_t)n * TS;
#pragma unroll
    for (int mi = 0; mi < 4; mi++) {
#pragma unroll
        for (int ni = 0; ni < 4; ni++) {
            int t = by * 128 + wm * 64 + mi * 16 + g;
            int s = bx * 128 + wn * 32 + ni * 8 + 2 * tg;
            *(float2*)(Cn + (size_t)t * SDIM + s)       = make_float2(acc[mi][ni][0], acc[mi][ni][1]);
            *(float2*)(Cn + (size_t)(t + 8) * SDIM + s) = make_float2(acc[mi][ni][2], acc[mi][ni][3]);
        }
    }
}

// ---------------------------------------------------------------------------
// Cross-head projection of one point (x[32] in regs -> out[32]).
// ---------------------------------------------------------------------------
__device__ __forceinline__ void chp_point(
    const float* __restrict__ x,
    const float* __restrict__ sws,   // smem [32][32]
    const float* __restrict__ qw1s,  // smem [2][32]
    const float* __restrict__ qw2s,  // smem [2][32]
    const float* __restrict__ qdds,  // smem [32]
    const float4* __restrict__ kw1v, // gmem, row s
    const float4* __restrict__ kw2v, // gmem, row s
    const float4* __restrict__ kddv, // gmem, row s
    float* __restrict__ out) {
    float qh0 = 0.f, qh1 = 0.f, kh0 = 0.f, kh1 = 0.f;
    const float4* qw1v = (const float4*)qw1s;
#pragma unroll
    for (int j = 0; j < 8; j++) {
        float4 a = qw1v[j];
        float4 b = qw1v[8 + j];
        float4 c = kw1v[j];
        float4 d = kw1v[8 + j];
        float x0 = x[4 * j], x1 = x[4 * j + 1], x2 = x[4 * j + 2], x3 = x[4 * j + 3];
        qh0 += x0 * a.x + x1 * a.y + x2 * a.z + x3 * a.w;
        qh1 += x0 * b.x + x1 * b.y + x2 * b.z + x3 * b.w;
        kh0 += x0 * c.x + x1 * c.y + x2 * c.z + x3 * c.w;
        kh1 += x0 * d.x + x1 * d.y + x2 * d.z + x3 * d.w;
    }
    const float4* qw2v = (const float4*)qw2s;
    const float4* qddv = (const float4*)qdds;
    const float4* swv  = (const float4*)sws;
#pragma unroll
    for (int mc = 0; mc < 8; mc++) {
        float4 q2a = qw2v[mc];
        float4 q2b = qw2v[8 + mc];
        float4 k2a = kw2v[mc];
        float4 k2b = kw2v[8 + mc];
        float4 kd  = kddv[mc];
        float4 qd  = qddv[mc];
        int m0 = mc * 4;
        float a0 = x[m0 + 0] * (1.f + qd.x + kd.x) + qh0 * q2a.x + qh1 * q2b.x + kh0 * k2a.x + kh1 * k2b.x;
        float a1 = x[m0 + 1] * (1.f + qd.y + kd.y) + qh0 * q2a.y + qh1 * q2b.y + kh0 * k2a.y + kh1 * k2b.y;
        float a2 = x[m0 + 2] * (1.f + qd.z + kd.z) + qh0 * q2a.z + qh1 * q2b.z + kh0 * k2a.z + kh1 * k2b.z;
        float a3 = x[m0 + 3] * (1.f + qd.w + kd.w) + qh0 * q2a.w + qh1 * q2b.w + kh0 * k2a.w + kh1 * k2b.w;
#pragma unroll
        for (int n = 0; n < 32; n++) {
            float4 w = swv[n * 8 + mc];
            float xn = x[n];
            a0 += xn * w.x;
            a1 += xn * w.y;
            a2 += xn * w.z;
            a3 += xn * w.w;
        }
        out[m0 + 0] = a0;
        out[m0 + 1] = a1;
        out[m0 + 2] = a2;
        out[m0 + 3] = a3;
    }
}

// ---------------------------------------------------------------------------
// K2 (fused middle): per t-row CTA: pre-proj -> softmax -> post-proj.
// Zero-fills probs out to a 128 boundary (AV reads 128-wide tiles).
// ---------------------------------------------------------------------------
#define PSTRIDE 1025
#define MID_THREADS 512
#define MID_SMEM_FLOATS (32 * PSTRIDE + 2048 + 256 + 64)

extern __shared__ float s_mid[];

__global__ __launch_bounds__(MID_THREADS, 1) void middle_kernel(
    const float* __restrict__ sw_pre,
    const float* __restrict__ qw1_pre, const float* __restrict__ qw2_pre,
    const float* __restrict__ kw1_pre, const float* __restrict__ kw2_pre,
    const float* __restrict__ qdd_pre, const float* __restrict__ kdd_pre,
    const float* __restrict__ sw_post,
    const float* __restrict__ qw1_post, const float* __restrict__ qw2_post,
    const float* __restrict__ kw1_post, const float* __restrict__ kw2_post,
    const float* __restrict__ qdd_post, const float* __restrict__ kdd_post) {
    int t = 1023 - blockIdx.x;  // longest rows first
    int len = t + 1;
    int pad = ((t >> 7) + 1) << 7;  // AV reads s < pad (128-wide tiles)
    int tid = threadIdx.x;

    float* P    = s_mid;
    float* swp  = s_mid + 32 * PSTRIDE;
    float* swo  = swp + 1024;
    float* qw1p = swo + 1024;
    float* qw2p = qw1p + 64;
    float* qw1o = qw2p + 64;
    float* qw2o = qw1o + 64;
    float* qddp = qw2o + 64;
    float* qddo = qddp + 32;

    for (int l = tid; l < 1024; l += MID_THREADS) {
        swp[l] = sw_pre[l];
        swo[l] = sw_post[l];
    }
    if (tid < 64) qw1p[tid] = qw1_pre[t * 64 + tid];
    else if (tid < 128) qw2p[tid - 64] = qw2_pre[t * 64 + tid - 64];
    else if (tid < 192) qw1o[tid - 128] = qw1_post[t * 64 + tid - 128];
    else if (tid < 256) qw2o[tid - 192] = qw2_post[t * 64 + tid - 192];
    else if (tid < 288) qddp[tid - 256] = qdd_pre[t * 32 + tid - 256];
    else if (tid < 320) qddo[tid - 288] = qdd_post[t * 32 + tid - 288];
    __syncthreads();

    // phase 1: pre-projection g_A -> P
    for (int s = tid; s < len; s += MID_THREADS) {
        const float* xg = g_A + (size_t)t * SDIM + s;
        float x[32];
#pragma unroll
        for (int n = 0; n < 32; n++) x[n] = xg[(size_t)n * TS];
        float out[32];
        chp_point(x, swp, qw1p, qw2p, qddp,
                  (const float4*)(kw1_pre + (size_t)s * 64),
                  (const float4*)(kw2_pre + (size_t)s * 64),
                  (const float4*)(kdd_pre + (size_t)s * 32),
                  out);
#pragma unroll
        for (int m = 0; m < 32; m++) P[m * PSTRIDE + s] = out[m];
    }
    __syncthreads();

    // phase 2: softmax per head (warp per head)
    int warp = tid >> 5, lane = tid & 31;
    for (int h = warp; h < 32; h += 16) {
        float* row = P + h * PSTRIDE;
        float mx = -CUDART_INF_F;
        for (int s = lane; s < len; s += 32) mx = fmaxf(mx, row[s]);
#pragma unroll
        for (int o = 16; o; o >>= 1) mx = fmaxf(mx, __shfl_xor_sync(~0u, mx, o));
        float Z = 0.f;
        for (int s = lane; s < len; s += 32) {
            float e = __expf(row[s] - mx);
            row[s] = e;
            Z += e;
        }
#pragma unroll
        for (int o = 16; o; o >>= 1) Z += __shfl_xor_sync(~0u, Z, o);
        float inv = 1.0f / Z;
        for (int s = lane; s < len; s += 32) row[s] *= inv;
    }
    __syncthreads();

    // phase 3: post-projection P -> g_B (+ zero fill to pad)
    for (int s = tid; s < pad; s += MID_THREADS) {
        float* dst = g_B + (size_t)t * SDIM + s;
        if (s < len) {
            float x[32];
#pragma unroll
            for (int n = 0; n < 32; n++) x[n] = P[n * PSTRIDE + s];
            float out[32];
            chp_point(x, swo, qw1o, qw2o, qddo,
                      (const float4*)(kw1_post + (size_t)s * 64),
                      (const float4*)(kw2_post + (size_t)s * 64),
                      (const float4*)(kdd_post + (size_t)s * 32),
                      out);
#pragma unroll
            for (int m = 0; m < 32; m++) dst[(size_t)m * TS] = out[m];
        } else {
#pragma unroll
            for (int m = 0; m < 32; m++) dst[(size_t)m * TS] = 0.0f;
        }
    }
}

// ---------------------------------------------------------------------------
// K3: out[n,t,d] = sum_s P[n,t,s]*V[n,s,d], tf32 tensor cores.
// Block tile 128(t) x 128(d), K (=s) chunks of 64, causal chunk bound.
// Ps stride 68 (mod 32 == 4); Vs stride 136 (mod 32 == 8): conflict-free frags.
// ---------------------------------------------------------------------------
#define PS_STR 68
#define VS_STR 136
#define AV_SMEM_BYTES ((128 * PS_STR + 64 * VS_STR) * 4)

__global__ __launch_bounds__(256) void av_gemm(const float* __restrict__ V,
                                               float* __restrict__ out) {
    int tt = 7 - blockIdx.x;  // longest first
    int n  = blockIdx.y;

    extern __shared__ uint32_t sm_av[];
    uint32_t* Ps = sm_av;                 // [128][68]
    uint32_t* Vs = sm_av + 128 * PS_STR;  // [64][136]

    const float* Pn = g_B + (size_t)n * TS + (size_t)tt * 128 * SDIM;
    const float* Vn = V + (size_t)n * SDIM * DDIM;

    int tid = threadIdx.x;
    int lane = tid & 31, warp = tid >> 5;
    int wm = warp >> 2, wn = warp & 3;
    int g = lane >> 2, tg = lane & 3;

    float acc[4][4][4] = {};
    int nchunks = 2 * (tt + 1);
    for (int c = 0; c < nchunks; c++) {
        int s0 = c * 64;
        // stage P 128x64
#pragma unroll
        for (int i = 0; i < 8; i++) {
            int idx = tid + i * 256;
            int r = idx >> 4, c4 = idx & 15;
            float4 p = *(const float4*)(Pn + (size_t)r * SDIM + s0 + c4 * 4);
            uint32_t* pd = Ps + r * PS_STR + c4 * 4;
            pd[0] = f2tf32(p.x); pd[1] = f2tf32(p.y); pd[2] = f2tf32(p.z); pd[3] = f2tf32(p.w);
        }
        // stage V 64x128
#pragma unroll
        for (int i = 0; i < 8; i++) {
            int idx = tid + i * 256;
            int r = idx >> 5, c4 = idx & 31;
            float4 v = *(const float4*)(Vn + (size_t)(s0 + r) * DDIM + c4 * 4);
            uint32_t* vd = Vs + r * VS_STR + c4 * 4;
            vd[0] = f2tf32(v.x); vd[1] = f2tf32(v.y); vd[2] = f2tf32(v.z); vd[3] = f2tf32(v.w);
        }
        __syncthreads();

#pragma unroll
        for (int ks = 0; ks < 64; ks += 8) {
            uint32_t a[4][4], b[4][2];
#pragma unroll
            for (int mi = 0; mi < 4; mi++) {
                int rb = wm * 64 + mi * 16;
                a[mi][0] = Ps[(rb + g) * PS_STR + ks + tg];
                a[mi][1] = Ps[(rb + g + 8) * PS_STR + ks + tg];
                a[mi][2] = Ps[(rb + g) * PS_STR + ks + tg + 4];
                a[mi][3] = Ps[(rb + g + 8) * PS_STR + ks + tg + 4];
            }
#pragma unroll
            for (int ni = 0; ni < 4; ni++) {
                int nb = wn * 32 + ni * 8;
                b[ni][0] = Vs[(ks + tg) * VS_STR + nb + g];
                b[ni][1] = Vs[(ks + tg + 4) * VS_STR + nb + g];
            }
#pragma unroll
            for (int mi = 0; mi < 4; mi++)
#pragma unroll
                for (int ni = 0; ni < 4; ni++) mma_tf32(acc[mi][ni], a[mi], b[ni]);
        }
        __syncthreads();
    }

#pragma unroll
    for (int mi = 0; mi < 4; mi++) {
#pragma unroll
        for (int ni = 0; ni < 4; ni++) {
            int t = tt * 128 + wm * 64 + mi * 16 + g;
            int d = wn * 32 + ni * 8 + 2 * tg;
            *(float2*)(out + ((size_t)n * TDIM + t) * DDIM + d)       = make_float2(acc[mi][ni][0], acc[mi][ni][1]);
            *(float2*)(out + ((size_t)n * TDIM + t + 8) * DDIM + d)   = make_float2(acc[mi][ni][2], acc[mi][ni][3]);
        }
    }
}

// ---------------------------------------------------------------------------
// Launch
// ---------------------------------------------------------------------------
extern "C" void kernel_launch(void* const* d_in, const int* in_sizes, int n_in,
                              void* d_out, int out_size) {
    const float* query = (const float*)d_in[0];
    const float* key   = (const float*)d_in[1];
    const float* value = (const float*)d_in[2];
    const float* sw_pre  = (const float*)d_in[4];
    const float* qw1_pre = (const float*)d_in[5];
    const float* qw2_pre = (const float*)d_in[6];
    const float* kw1_pre = (const float*)d_in[7];
    const float* kw2_pre = (const float*)d_in[8];
    const float* qdd_pre = (const float*)d_in[9];
    const float* kdd_pre = (const float*)d_in[10];
    const float* sw_post  = (const float*)d_in[11];
    const float* qw1_post = (const float*)d_in[12];
    const float* qw2_post = (const float*)d_in[13];
    const float* kw1_post = (const float*)d_in[14];
    const float* kw2_post = (const float*)d_in[15];
    const float* qdd_post = (const float*)d_in[16];
    const float* kdd_post = (const float*)d_in[17];
    float* out = (float*)d_out;

    size_t mid_smem = MID_SMEM_FLOATS * sizeof(float);
    cudaFuncSetAttribute(middle_kernel, cudaFuncAttributeMaxDynamicSharedMemorySize, (int)mid_smem);
    cudaFuncSetAttribute(qk_gemm, cudaFuncAttributeMaxDynamicSharedMemorySize, QK_SMEM_BYTES);
    cudaFuncSetAttribute(av_gemm, cudaFuncAttributeMaxDynamicSharedMemorySize, AV_SMEM_BYTES);

    qk_gemm<<<dim3(8, 8, 32), 256, QK_SMEM_BYTES>>>(query, key);
    middle_kernel<<<1024, MID_THREADS, mid_smem>>>(
        sw_pre, qw1_pre, qw2_pre, kw1_pre, kw2_pre, qdd_pre, kdd_pre,
        sw_post, qw1_post, qw2_post, kw1_post, kw2_post, qdd_post, kdd_post);
    av_gemm<<<dim3(8, 32), 256, AV_SMEM_BYTES>>>(value, out);
}

// round 4
// speedup vs baseline: 3.8068x; 1.2628x over previous
#include <cuda_runtime.h>
#include <cuda_bf16.h>
#include <math_constants.h>
#include <cstdint>

#define NH 32
#define TDIM 1024
#define SDIM 1024
#define DDIM 128
#define TS (TDIM * SDIM)

__device__ float g_A[(size_t)NH * TS];   // raw logits (QK output)
__device__ float g_B[(size_t)NH * TS];   // final probs (AV input)

// ---------------------------------------------------------------------------
// tf32 helpers
// ---------------------------------------------------------------------------
__device__ __forceinline__ uint32_t f2tf32(float f) {
    uint32_t u;
    asm("cvt.rna.tf32.f32 %0, %1;" : "=r"(u) : "f"(f));
    return u;
}

__device__ __forceinline__ void mma_tf32(float* c, const uint32_t* a, const uint32_t* b) {
    asm volatile(
        "mma.sync.aligned.m16n8k8.row.col.f32.tf32.tf32.f32 "
        "{%0,%1,%2,%3}, {%4,%5,%6,%7}, {%8,%9}, {%0,%1,%2,%3};"
        : "+f"(c[0]), "+f"(c[1]), "+f"(c[2]), "+f"(c[3])
        : "r"(a[0]), "r"(a[1]), "r"(a[2]), "r"(a[3]), "r"(b[0]), "r"(b[1]));
}

// ---------------------------------------------------------------------------
// K1: QK^T tf32 tensor-core GEMM (causal tiles only). 128x128 block tile.
// ---------------------------------------------------------------------------
#define QK_STR 68
#define QK_SMEM_BYTES (2 * 128 * QK_STR * 4)

__global__ __launch_bounds__(256) void qk_gemm(const float* __restrict__ Q,
                                               const float* __restrict__ K) {
    int bx = blockIdx.x, by = blockIdx.y, n = blockIdx.z;
    if (bx > by) return;

    extern __shared__ uint32_t sm_qk[];
    uint32_t* Qs = sm_qk;
    uint32_t* Ks = sm_qk + 128 * QK_STR;

    const float* Qn = Q + ((size_t)n * TDIM + by * 128) * DDIM;
    const float* Kn = K + ((size_t)n * SDIM + bx * 128) * DDIM;

    int tid = threadIdx.x;
    int lane = tid & 31, warp = tid >> 5;
    int wm = warp >> 2, wn = warp & 3;
    int g = lane >> 2, tg = lane & 3;

    float acc[4][4][4] = {};

    for (int k0 = 0; k0 < DDIM; k0 += 64) {
#pragma unroll
        for (int i = 0; i < 8; i++) {
            int idx = tid + i * 256;
            int r = idx >> 4, c4 = idx & 15;
            float4 q = *(const float4*)(Qn + (size_t)r * DDIM + k0 + c4 * 4);
            float4 k = *(const float4*)(Kn + (size_t)r * DDIM + k0 + c4 * 4);
            uint32_t* qd = Qs + r * QK_STR + c4 * 4;
            uint32_t* kd = Ks + r * QK_STR + c4 * 4;
            qd[0] = f2tf32(q.x); qd[1] = f2tf32(q.y); qd[2] = f2tf32(q.z); qd[3] = f2tf32(q.w);
            kd[0] = f2tf32(k.x); kd[1] = f2tf32(k.y); kd[2] = f2tf32(k.z); kd[3] = f2tf32(k.w);
        }
        __syncthreads();

#pragma unroll
        for (int ks = 0; ks < 64; ks += 8) {
            uint32_t a[4][4], b[4][2];
#pragma unroll
            for (int mi = 0; mi < 4; mi++) {
                int rb = wm * 64 + mi * 16;
                a[mi][0] = Qs[(rb + g) * QK_STR + ks + tg];
                a[mi][1] = Qs[(rb + g + 8) * QK_STR + ks + tg];
                a[mi][2] = Qs[(rb + g) * QK_STR + ks + tg + 4];
                a[mi][3] = Qs[(rb + g + 8) * QK_STR + ks + tg + 4];
            }
#pragma unroll
            for (int ni = 0; ni < 4; ni++) {
                int nb = wn * 32 + ni * 8;
                b[ni][0] = Ks[(nb + g) * QK_STR + ks + tg];
                b[ni][1] = Ks[(nb + g) * QK_STR + ks + tg + 4];
            }
#pragma unroll
            for (int mi = 0; mi < 4; mi++)
#pragma unroll
                for (int ni = 0; ni < 4; ni++) mma_tf32(acc[mi][ni], a[mi], b[ni]);
        }
        __syncthreads();
    }

    float* Cn = g_A + (size_t)n * TS;
#pragma unroll
    for (int mi = 0; mi < 4; mi++) {
#pragma unroll
        for (int ni = 0; ni < 4; ni++) {
            int t = by * 128 + wm * 64 + mi * 16 + g;
            int s = bx * 128 + wn * 32 + ni * 8 + 2 * tg;
            *(float2*)(Cn + (size_t)t * SDIM + s)       = make_float2(acc[mi][ni][0], acc[mi][ni][1]);
            *(float2*)(Cn + (size_t)(t + 8) * SDIM + s) = make_float2(acc[mi][ni][2], acc[mi][ni][3]);
        }
    }
}

// ---------------------------------------------------------------------------
// Middle kernel: per-t CTA. P[s][36] fp32 in smem.
//   pre-proj: tensor-core W_eff mix + fp32 k-terms/identity  (in-place)
//   softmax (unnormalized exp; 1/Z folded into post-proj loads)
//   post-proj: same structure
// ---------------------------------------------------------------------------
#define PROW 36
#define MID_THREADS 512
// floats: P 1024*36 | WTp 1152(u32) | WTo 1152(u32) | red 16*33 | gmax 32 | ginv 32
#define MID_SMEM_FLOATS (36864 + 1152 + 1152 + 528 + 32 + 32)

extern __shared__ float s_mid[];

// Projection: rows(s) x heads GEMM via m16n8k8 tf32 + fp32 epilogue.
// SCALED: multiply every X read by ginv[head] (post-softmax normalization).
template <bool SCALED>
__device__ __forceinline__ void do_proj(
    float* __restrict__ P, const uint32_t* __restrict__ WT,
    const float* __restrict__ ginv,
    const float* __restrict__ kw1, const float* __restrict__ kw2,
    const float* __restrict__ kdd, int len, int warp, int lane) {
    int g = lane >> 2, tg = lane & 3;

    uint32_t b[4][4][2];  // [ktile][ntile][2]
#pragma unroll
    for (int kt = 0; kt < 4; kt++)
#pragma unroll
        for (int ni = 0; ni < 4; ni++) {
            b[kt][ni][0] = WT[(ni * 8 + g) * PROW + kt * 8 + tg];
            b[kt][ni][1] = WT[(ni * 8 + g) * PROW + kt * 8 + tg + 4];
        }

    int nchunks = (len + 15) >> 4;
    for (int c = warp; c < nchunks; c += 16) {
        int s0 = c * 16;
        float cacc[4][4] = {};
#pragma unroll
        for (int kt = 0; kt < 4; kt++) {
            int k0 = kt * 8;
            float f0 = P[(s0 + g) * PROW + k0 + tg];
            float f1 = P[(s0 + g + 8) * PROW + k0 + tg];
            float f2 = P[(s0 + g) * PROW + k0 + tg + 4];
            float f3 = P[(s0 + g + 8) * PROW + k0 + tg + 4];
            if (SCALED) {
                float i0 = ginv[k0 + tg], i1 = ginv[k0 + tg + 4];
                f0 *= i0; f1 *= i0; f2 *= i1; f3 *= i1;
            }
            uint32_t a[4] = {f2tf32(f0), f2tf32(f1), f2tf32(f2), f2tf32(f3)};
#pragma unroll
            for (int ni = 0; ni < 4; ni++) mma_tf32(cacc[ni], a, b[kt][ni]);
        }

        // k-side rank-2 partial dots (cross-lane X reads happen BEFORE the shfl)
        float kh0[2], kh1[2];
#pragma unroll
        for (int rr = 0; rr < 2; rr++) {
            int s = s0 + g + rr * 8;
            float4 xa = *(const float4*)(P + s * PROW + tg * 8);
            float4 xb = *(const float4*)(P + s * PROW + tg * 8 + 4);
            if (SCALED) {
                float4 ia = *(const float4*)(ginv + tg * 8);
                float4 ib = *(const float4*)(ginv + tg * 8 + 4);
                xa.x *= ia.x; xa.y *= ia.y; xa.z *= ia.z; xa.w *= ia.w;
                xb.x *= ib.x; xb.y *= ib.y; xb.z *= ib.z; xb.w *= ib.w;
            }
            float4 wa = *(const float4*)(kw1 + (size_t)s * 64 + tg * 8);
            float4 wb = *(const float4*)(kw1 + (size_t)s * 64 + tg * 8 + 4);
            float4 wc = *(const float4*)(kw1 + (size_t)s * 64 + 32 + tg * 8);
            float4 wd = *(const float4*)(kw1 + (size_t)s * 64 + 32 + tg * 8 + 4);
            kh0[rr] = xa.x * wa.x + xa.y * wa.y + xa.z * wa.z + xa.w * wa.w
                    + xb.x * wb.x + xb.y * wb.y + xb.z * wb.z + xb.w * wb.w;
            kh1[rr] = xa.x * wc.x + xa.y * wc.y + xa.z * wc.z + xa.w * wc.w
                    + xb.x * wd.x + xb.y * wd.y + xb.z * wd.z + xb.w * wd.w;
        }
#pragma unroll
        for (int o = 1; o <= 2; o <<= 1) {
            kh0[0] += __shfl_xor_sync(~0u, kh0[0], o);
            kh0[1] += __shfl_xor_sync(~0u, kh0[1], o);
            kh1[0] += __shfl_xor_sync(~0u, kh1[0], o);
            kh1[1] += __shfl_xor_sync(~0u, kh1[1], o);
        }
        // epilogue: identity + kdd diag + k-rank2, store in place (own cols only)
#pragma unroll
        for (int rr = 0; rr < 2; rr++) {
            int s = s0 + g + rr * 8;
#pragma unroll
            for (int ni = 0; ni < 4; ni++) {
                int col = ni * 8 + 2 * tg;
                float2 xv = *(const float2*)(P + s * PROW + col);
                if (SCALED) { xv.x *= ginv[col]; xv.y *= ginv[col + 1]; }
                float2 k20 = *(const float2*)(kw2 + (size_t)s * 64 + col);
                float2 k21 = *(const float2*)(kw2 + (size_t)s * 64 + 32 + col);
                float2 kd  = *(const float2*)(kdd + (size_t)s * 32 + col);
                float o0 = cacc[ni][rr * 2 + 0] + kh0[rr] * k20.x + kh1[rr] * k21.x + xv.x * (1.f + kd.x);
                float o1 = cacc[ni][rr * 2 + 1] + kh0[rr] * k20.y + kh1[rr] * k21.y + xv.y * (1.f + kd.y);
                *(float2*)(P + s * PROW + col) = make_float2(o0, o1);
            }
        }
    }
}

__global__ __launch_bounds__(MID_THREADS, 1) void middle_kernel(
    const float* __restrict__ sw_pre,
    const float* __restrict__ qw1_pre, const float* __restrict__ qw2_pre,
    const float* __restrict__ kw1_pre, const float* __restrict__ kw2_pre,
    const float* __restrict__ qdd_pre, const float* __restrict__ kdd_pre,
    const float* __restrict__ sw_post,
    const float* __restrict__ qw1_post, const float* __restrict__ qw2_post,
    const float* __restrict__ kw1_post, const float* __restrict__ kw2_post,
    const float* __restrict__ qdd_post, const float* __restrict__ kdd_post) {
    float* P = s_mid;                                 // [1024][36]
    uint32_t* WTp = (uint32_t*)(s_mid + 36864);       // [32][36] tf32 bits
    uint32_t* WTo = WTp + 1152;
    float* red  = (float*)(WTo + 1152);               // [16][33]
    float* gmax = red + 528;                          // [32]
    float* ginv = gmax + 32;                          // [32]

    int t = 1023 - blockIdx.x;   // longest rows first
    int len = t + 1;
    int pad = ((t >> 7) + 1) << 7;
    int tid = threadIdx.x;
    int warp = tid >> 5, lane = tid & 31;

    // Build effective per-t head-mixing matrices (transposed, tf32 bits).
    // W_eff[n][m] = sw[n][m] + sum_i qw1[t,i,n]*qw2[t,i,m] + (n==m)*qdd[t,m]
    // (identity deliberately NOT included: kept exact fp32 in epilogue)
    for (int idx = tid; idx < 2048; idx += MID_THREADS) {
        int which = idx >> 10;
        int r = idx & 1023;
        int n = r >> 5, m = r & 31;
        const float* sw = which ? sw_post : sw_pre;
        const float* q1 = which ? qw1_post : qw1_pre;
        const float* q2 = which ? qw2_post : qw2_pre;
        const float* qd = which ? qdd_post : qdd_pre;
        float w = sw[n * 32 + m] + q1[t * 64 + n] * q2[t * 64 + m]
                + q1[t * 64 + 32 + n] * q2[t * 64 + 32 + m];
        if (n == m) w += qd[t * 32 + m];
        (which ? WTo : WTp)[m * PROW + n] = f2tf32(w);
    }

    // Phase A: stage logits g_A[n][t][:] -> P[s][n]
    {
        int s = tid * 4;
        if (s < len) {
            for (int n = 0; n < 32; n++) {
                float4 v = *(const float4*)(g_A + (size_t)n * TS + (size_t)t * SDIM + s);
                P[s * PROW + n] = v.x;
                P[(s + 1) * PROW + n] = v.y;
                P[(s + 2) * PROW + n] = v.z;
                P[(s + 3) * PROW + n] = v.w;
            }
        }
    }
    __syncthreads();

    // Pre-projection (in place)
    do_proj<false>(P, WTp, nullptr, kw1_pre, kw2_pre, kdd_pre, len, warp, lane);
    __syncthreads();

    // Softmax over s per head (lane = head, warps split s; exp left unnormalized)
    {
        float mx = -CUDART_INF_F;
        for (int s = warp; s < len; s += 16) mx = fmaxf(mx, P[s * PROW + lane]);
        red[warp * 33 + lane] = mx;
        __syncthreads();
        if (tid < 32) {
            float m = red[tid];
#pragma unroll
            for (int w = 1; w < 16; w++) m = fmaxf(m, red[w * 33 + tid]);
            gmax[tid] = m;
        }
        __syncthreads();
        float gm = gmax[lane];
        float Z = 0.f;
        for (int s = warp; s < len; s += 16) {
            float e = __expf(P[s * PROW + lane] - gm);
            P[s * PROW + lane] = e;
            Z += e;
        }
        red[warp * 33 + lane] = Z;
        __syncthreads();
        if (tid < 32) {
            float z = 0.f;
#pragma unroll
            for (int w = 0; w < 16; w++) z += red[w * 33 + tid];
            ginv[tid] = 1.0f / z;
        }
        __syncthreads();
    }

    // Post-projection (input scaled by ginv at every read)
    do_proj<true>(P, WTo, ginv, kw1_post, kw2_post, kdd_post, len, warp, lane);
    __syncthreads();

    // Phase E: P[s][n] -> g_B[n][t][s], zero-fill to 128 boundary
    {
        int s = tid * 4;
        if (s < pad) {
            for (int n = 0; n < 32; n++) {
                float4 v;
                v.x = (s     < len) ? P[s * PROW + n] : 0.f;
                v.y = (s + 1 < len) ? P[(s + 1) * PROW + n] : 0.f;
                v.z = (s + 2 < len) ? P[(s + 2) * PROW + n] : 0.f;
                v.w = (s + 3 < len) ? P[(s + 3) * PROW + n] : 0.f;
                *(float4*)(g_B + (size_t)n * TS + (size_t)t * SDIM + s) = v;
            }
        }
    }
}

// ---------------------------------------------------------------------------
// K3: AV tf32 tensor-core GEMM. 128(t) x 128(d), causal chunk bound.
// ---------------------------------------------------------------------------
#define PS_STR 68
#define VS_STR 136
#define AV_SMEM_BYTES ((128 * PS_STR + 64 * VS_STR) * 4)

__global__ __launch_bounds__(256) void av_gemm(const float* __restrict__ V,
                                               float* __restrict__ out) {
    int tt = 7 - blockIdx.x;
    int n  = blockIdx.y;

    extern __shared__ uint32_t sm_av[];
    uint32_t* Ps = sm_av;
    uint32_t* Vs = sm_av + 128 * PS_STR;

    const float* Pn = g_B + (size_t)n * TS + (size_t)tt * 128 * SDIM;
    const float* Vn = V + (size_t)n * SDIM * DDIM;

    int tid = threadIdx.x;
    int lane = tid & 31, warp = tid >> 5;
    int wm = warp >> 2, wn = warp & 3;
    int g = lane >> 2, tg = lane & 3;

    float acc[4][4][4] = {};
    int nchunks = 2 * (tt + 1);
    for (int c = 0; c < nchunks; c++) {
        int s0 = c * 64;
#pragma unroll
        for (int i = 0; i < 8; i++) {
            int idx = tid + i * 256;
            int r = idx >> 4, c4 = idx & 15;
            float4 p = *(const float4*)(Pn + (size_t)r * SDIM + s0 + c4 * 4);
            uint32_t* pd = Ps + r * PS_STR + c4 * 4;
            pd[0] = f2tf32(p.x); pd[1] = f2tf32(p.y); pd[2] = f2tf32(p.z); pd[3] = f2tf32(p.w);
        }
#pragma unroll
        for (int i = 0; i < 8; i++) {
            int idx = tid + i * 256;
            int r = idx >> 5, c4 = idx & 31;
            float4 v = *(const float4*)(Vn + (size_t)(s0 + r) * DDIM + c4 * 4);
            uint32_t* vd = Vs + r * VS_STR + c4 * 4;
            vd[0] = f2tf32(v.x); vd[1] = f2tf32(v.y); vd[2] = f2tf32(v.z); vd[3] = f2tf32(v.w);
        }
        __syncthreads();

#pragma unroll
        for (int ks = 0; ks < 64; ks += 8) {
            uint32_t a[4][4], b[4][2];
#pragma unroll
            for (int mi = 0; mi < 4; mi++) {
                int rb = wm * 64 + mi * 16;
                a[mi][0] = Ps[(rb + g) * PS_STR + ks + tg];
                a[mi][1] = Ps[(rb + g + 8) * PS_STR + ks + tg];
                a[mi][2] = Ps[(rb + g) * PS_STR + ks + tg + 4];
                a[mi][3] = Ps[(rb + g + 8) * PS_STR + ks + tg + 4];
            }
#pragma unroll
            for (int ni = 0; ni < 4; ni++) {
                int nb = wn * 32 + ni * 8;
                b[ni][0] = Vs[(ks + tg) * VS_STR + nb + g];
                b[ni][1] = Vs[(ks + tg + 4) * VS_STR + nb + g];
            }
#pragma unroll
            for (int mi = 0; mi < 4; mi++)
#pragma unroll
                for (int ni = 0; ni < 4; ni++) mma_tf32(acc[mi][ni], a[mi], b[ni]);
        }
        __syncthreads();
    }

#pragma unroll
    for (int mi = 0; mi < 4; mi++) {
#pragma unroll
        for (int ni = 0; ni < 4; ni++) {
            int t = tt * 128 + wm * 64 + mi * 16 + g;
            int d = wn * 32 + ni * 8 + 2 * tg;
            *(float2*)(out + ((size_t)n * TDIM + t) * DDIM + d)     = make_float2(acc[mi][ni][0], acc[mi][ni][1]);
            *(float2*)(out + ((size_t)n * TDIM + t + 8) * DDIM + d) = make_float2(acc[mi][ni][2], acc[mi][ni][3]);
        }
    }
}

// ---------------------------------------------------------------------------
// Launch
// ---------------------------------------------------------------------------
extern "C" void kernel_launch(void* const* d_in, const int* in_sizes, int n_in,
                              void* d_out, int out_size) {
    const float* query = (const float*)d_in[0];
    const float* key   = (const float*)d_in[1];
    const float* value = (const float*)d_in[2];
    const float* sw_pre  = (const float*)d_in[4];
    const float* qw1_pre = (const float*)d_in[5];
    const float* qw2_pre = (const float*)d_in[6];
    const float* kw1_pre = (const float*)d_in[7];
    const float* kw2_pre = (const float*)d_in[8];
    const float* qdd_pre = (const float*)d_in[9];
    const float* kdd_pre = (const float*)d_in[10];
    const float* sw_post  = (const float*)d_in[11];
    const float* qw1_post = (const float*)d_in[12];
    const float* qw2_post = (const float*)d_in[13];
    const float* kw1_post = (const float*)d_in[14];
    const float* kw2_post = (const float*)d_in[15];
    const float* qdd_post = (const float*)d_in[16];
    const float* kdd_post = (const float*)d_in[17];
    float* out = (float*)d_out;

    size_t mid_smem = MID_SMEM_FLOATS * sizeof(float);
    cudaFuncSetAttribute(middle_kernel, cudaFuncAttributeMaxDynamicSharedMemorySize, (int)mid_smem);
    cudaFuncSetAttribute(qk_gemm, cudaFuncAttributeMaxDynamicSharedMemorySize, QK_SMEM_BYTES);
    cudaFuncSetAttribute(av_gemm, cudaFuncAttributeMaxDynamicSharedMemorySize, AV_SMEM_BYTES);

    qk_gemm<<<dim3(8, 8, 32), 256, QK_SMEM_BYTES>>>(query, key);
    middle_kernel<<<1024, MID_THREADS, mid_smem>>>(
        sw_pre, qw1_pre, qw2_pre, kw1_pre, kw2_pre, qdd_pre, kdd_pre,
        sw_post, qw1_post, qw2_post, kw1_post, kw2_post, qdd_post, kdd_post);
    av_gemm<<<dim3(8, 32), 256, AV_SMEM_BYTES>>>(value, out);
}

// round 5
// speedup vs baseline: 3.9041x; 1.0256x over previous
#include <cuda_runtime.h>
#include <cuda_bf16.h>
#include <math_constants.h>
#include <cstdint>

#define NH 32
#define TDIM 1024
#define SDIM 1024
#define DDIM 128
#define TS (TDIM * SDIM)

__device__ float g_A[(size_t)NH * TS];   // raw logits (QK output)
__device__ float g_B[(size_t)NH * TS];   // final probs (AV input)

// ---------------------------------------------------------------------------
// tf32 helpers
// ---------------------------------------------------------------------------
__device__ __forceinline__ uint32_t f2tf32(float f) {
    uint32_t u;
    asm("cvt.rna.tf32.f32 %0, %1;" : "=r"(u) : "f"(f));
    return u;
}

__device__ __forceinline__ void mma_tf32(float* c, const uint32_t* a, const uint32_t* b) {
    asm volatile(
        "mma.sync.aligned.m16n8k8.row.col.f32.tf32.tf32.f32 "
        "{%0,%1,%2,%3}, {%4,%5,%6,%7}, {%8,%9}, {%0,%1,%2,%3};"
        : "+f"(c[0]), "+f"(c[1]), "+f"(c[2]), "+f"(c[3])
        : "r"(a[0]), "r"(a[1]), "r"(a[2]), "r"(a[3]), "r"(b[0]), "r"(b[1]));
}

// ---------------------------------------------------------------------------
// K1: QK^T tf32 GEMM, causal tiles linearized (36 tiles/head, no dead CTAs).
// ---------------------------------------------------------------------------
#define QK_STR 68
#define QK_SMEM_BYTES (2 * 128 * QK_STR * 4)

__global__ __launch_bounds__(256) void qk_gemm(const float* __restrict__ Q,
                                               const float* __restrict__ K) {
    int i = blockIdx.x;  // 0..35 triangular index
    int n = blockIdx.y;
    int by = 0;
    while ((by + 1) * (by + 2) / 2 <= i) by++;
    int bx = i - by * (by + 1) / 2;

    extern __shared__ uint32_t sm_qk[];
    uint32_t* Qs = sm_qk;
    uint32_t* Ks = sm_qk + 128 * QK_STR;

    const float* Qn = Q + ((size_t)n * TDIM + by * 128) * DDIM;
    const float* Kn = K + ((size_t)n * SDIM + bx * 128) * DDIM;

    int tid = threadIdx.x;
    int lane = tid & 31, warp = tid >> 5;
    int wm = warp >> 2, wn = warp & 3;
    int g = lane >> 2, tg = lane & 3;

    float acc[4][4][4] = {};

    for (int k0 = 0; k0 < DDIM; k0 += 64) {
#pragma unroll
        for (int ii = 0; ii < 8; ii++) {
            int idx = tid + ii * 256;
            int r = idx >> 4, c4 = idx & 15;
            float4 q = *(const float4*)(Qn + (size_t)r * DDIM + k0 + c4 * 4);
            float4 k = *(const float4*)(Kn + (size_t)r * DDIM + k0 + c4 * 4);
            uint32_t* qd = Qs + r * QK_STR + c4 * 4;
            uint32_t* kd = Ks + r * QK_STR + c4 * 4;
            qd[0] = f2tf32(q.x); qd[1] = f2tf32(q.y); qd[2] = f2tf32(q.z); qd[3] = f2tf32(q.w);
            kd[0] = f2tf32(k.x); kd[1] = f2tf32(k.y); kd[2] = f2tf32(k.z); kd[3] = f2tf32(k.w);
        }
        __syncthreads();

#pragma unroll
        for (int ks = 0; ks < 64; ks += 8) {
            uint32_t a[4][4], b[4][2];
#pragma unroll
            for (int mi = 0; mi < 4; mi++) {
                int rb = wm * 64 + mi * 16;
                a[mi][0] = Qs[(rb + g) * QK_STR + ks + tg];
                a[mi][1] = Qs[(rb + g + 8) * QK_STR + ks + tg];
                a[mi][2] = Qs[(rb + g) * QK_STR + ks + tg + 4];
                a[mi][3] = Qs[(rb + g + 8) * QK_STR + ks + tg + 4];
            }
#pragma unroll
            for (int ni = 0; ni < 4; ni++) {
                int nb = wn * 32 + ni * 8;
                b[ni][0] = Ks[(nb + g) * QK_STR + ks + tg];
                b[ni][1] = Ks[(nb + g) * QK_STR + ks + tg + 4];
            }
#pragma unroll
            for (int mi = 0; mi < 4; mi++)
#pragma unroll
                for (int ni = 0; ni < 4; ni++) mma_tf32(acc[mi][ni], a[mi], b[ni]);
        }
        __syncthreads();
    }

    float* Cn = g_A + (size_t)n * TS;
#pragma unroll
    for (int mi = 0; mi < 4; mi++) {
#pragma unroll
        for (int ni = 0; ni < 4; ni++) {
            int t = by * 128 + wm * 64 + mi * 16 + g;
            int s = bx * 128 + wn * 32 + ni * 8 + 2 * tg;
            *(float2*)(Cn + (size_t)t * SDIM + s)       = make_float2(acc[mi][ni][0], acc[mi][ni][1]);
            *(float2*)(Cn + (size_t)(t + 8) * SDIM + s) = make_float2(acc[mi][ni][2], acc[mi][ni][3]);
        }
    }
}

// ---------------------------------------------------------------------------
// Middle kernel: per-t CTA, 1024 threads (32 warps).
// ---------------------------------------------------------------------------
#define PROW 36
#define MID_THREADS 1024
// floats: P 36864 | WTp 1152 | WTo 1152 | red 32*33 | gmax 32 | ginv 32
#define MID_SMEM_FLOATS (36864 + 1152 + 1152 + 1056 + 32 + 32)

extern __shared__ float s_mid[];

template <bool SCALED>
__device__ __forceinline__ void do_proj(
    float* __restrict__ P, const uint32_t* __restrict__ WT,
    const float* __restrict__ ginv,
    const float* __restrict__ kw1, const float* __restrict__ kw2,
    const float* __restrict__ kdd, int len, int warp, int lane) {
    int g = lane >> 2, tg = lane & 3;

    int nchunks = (len + 15) >> 4;
    for (int c = warp; c < nchunks; c += 32) {
        int s0 = c * 16;
        float cacc[4][4] = {};
#pragma unroll
        for (int kt = 0; kt < 4; kt++) {
            int k0 = kt * 8;
            float f0 = P[(s0 + g) * PROW + k0 + tg];
            float f1 = P[(s0 + g + 8) * PROW + k0 + tg];
            float f2 = P[(s0 + g) * PROW + k0 + tg + 4];
            float f3 = P[(s0 + g + 8) * PROW + k0 + tg + 4];
            if (SCALED) {
                float i0 = ginv[k0 + tg], i1 = ginv[k0 + tg + 4];
                f0 *= i0; f1 *= i0; f2 *= i1; f3 *= i1;
            }
            uint32_t a[4] = {f2tf32(f0), f2tf32(f1), f2tf32(f2), f2tf32(f3)};
#pragma unroll
            for (int ni = 0; ni < 4; ni++) {
                uint32_t b[2];
                b[0] = WT[(ni * 8 + g) * PROW + k0 + tg];
                b[1] = WT[(ni * 8 + g) * PROW + k0 + tg + 4];
                mma_tf32(cacc[ni], a, b);
            }
        }

        // k-side rank-2 partial dots
        float kh0[2], kh1[2];
#pragma unroll
        for (int rr = 0; rr < 2; rr++) {
            int s = s0 + g + rr * 8;
            float4 xa = *(const float4*)(P + s * PROW + tg * 8);
            float4 xb = *(const float4*)(P + s * PROW + tg * 8 + 4);
            if (SCALED) {
                float4 ia = *(const float4*)(ginv + tg * 8);
                float4 ib = *(const float4*)(ginv + tg * 8 + 4);
                xa.x *= ia.x; xa.y *= ia.y; xa.z *= ia.z; xa.w *= ia.w;
                xb.x *= ib.x; xb.y *= ib.y; xb.z *= ib.z; xb.w *= ib.w;
            }
            float4 wa = *(const float4*)(kw1 + (size_t)s * 64 + tg * 8);
            float4 wb = *(const float4*)(kw1 + (size_t)s * 64 + tg * 8 + 4);
            float4 wc = *(const float4*)(kw1 + (size_t)s * 64 + 32 + tg * 8);
            float4 wd = *(const float4*)(kw1 + (size_t)s * 64 + 32 + tg * 8 + 4);
            kh0[rr] = xa.x * wa.x + xa.y * wa.y + xa.z * wa.z + xa.w * wa.w
                    + xb.x * wb.x + xb.y * wb.y + xb.z * wb.z + xb.w * wb.w;
            kh1[rr] = xa.x * wc.x + xa.y * wc.y + xa.z * wc.z + xa.w * wc.w
                    + xb.x * wd.x + xb.y * wd.y + xb.z * wd.z + xb.w * wd.w;
        }
#pragma unroll
        for (int o = 1; o <= 2; o <<= 1) {
            kh0[0] += __shfl_xor_sync(~0u, kh0[0], o);
            kh0[1] += __shfl_xor_sync(~0u, kh0[1], o);
            kh1[0] += __shfl_xor_sync(~0u, kh1[0], o);
            kh1[1] += __shfl_xor_sync(~0u, kh1[1], o);
        }
#pragma unroll
        for (int rr = 0; rr < 2; rr++) {
            int s = s0 + g + rr * 8;
#pragma unroll
            for (int ni = 0; ni < 4; ni++) {
                int col = ni * 8 + 2 * tg;
                float2 xv = *(const float2*)(P + s * PROW + col);
                if (SCALED) { xv.x *= ginv[col]; xv.y *= ginv[col + 1]; }
                float2 k20 = *(const float2*)(kw2 + (size_t)s * 64 + col);
                float2 k21 = *(const float2*)(kw2 + (size_t)s * 64 + 32 + col);
                float2 kd  = *(const float2*)(kdd + (size_t)s * 32 + col);
                float o0 = cacc[ni][rr * 2 + 0] + kh0[rr] * k20.x + kh1[rr] * k21.x + xv.x * (1.f + kd.x);
                float o1 = cacc[ni][rr * 2 + 1] + kh0[rr] * k20.y + kh1[rr] * k21.y + xv.y * (1.f + kd.y);
                *(float2*)(P + s * PROW + col) = make_float2(o0, o1);
            }
        }
    }
}

__global__ __launch_bounds__(MID_THREADS, 1) void middle_kernel(
    const float* __restrict__ sw_pre,
    const float* __restrict__ qw1_pre, const float* __restrict__ qw2_pre,
    const float* __restrict__ kw1_pre, const float* __restrict__ kw2_pre,
    const float* __restrict__ qdd_pre, const float* __restrict__ kdd_pre,
    const float* __restrict__ sw_post,
    const float* __restrict__ qw1_post, const float* __restrict__ qw2_post,
    const float* __restrict__ kw1_post, const float* __restrict__ kw2_post,
    const float* __restrict__ qdd_post, const float* __restrict__ kdd_post) {
    float* P = s_mid;                                 // [1024][36]
    uint32_t* WTp = (uint32_t*)(s_mid + 36864);       // [32][36] tf32 bits
    uint32_t* WTo = WTp + 1152;
    float* red  = (float*)(WTo + 1152);               // [32][33]
    float* gmax = red + 1056;                         // [32]
    float* ginv = gmax + 32;                          // [32]

    int t = 1023 - blockIdx.x;   // longest rows first
    int len = t + 1;
    int pad = ((t >> 7) + 1) << 7;
    int tid = threadIdx.x;
    int warp = tid >> 5, lane = tid & 31;

    // Effective per-t mixing matrices (transposed, tf32 bits); identity kept fp32.
    for (int idx = tid; idx < 2048; idx += MID_THREADS) {
        int which = idx >> 10;
        int r = idx & 1023;
        int n = r >> 5, m = r & 31;
        const float* sw = which ? sw_post : sw_pre;
        const float* q1 = which ? qw1_post : qw1_pre;
        const float* q2 = which ? qw2_post : qw2_pre;
        const float* qd = which ? qdd_post : qdd_pre;
        float w = sw[n * 32 + m] + q1[t * 64 + n] * q2[t * 64 + m]
                + q1[t * 64 + 32 + n] * q2[t * 64 + 32 + m];
        if (n == m) w += qd[t * 32 + m];
        (which ? WTo : WTp)[m * PROW + n] = f2tf32(w);
    }

    // Phase A: stage logits g_A[n][t][:] -> P[s][n] (all 1024 threads)
    for (int idx = tid; idx < 32 * 256; idx += MID_THREADS) {
        int n = idx >> 8;
        int s = (idx & 255) * 4;
        if (s < len) {
            float4 v = *(const float4*)(g_A + (size_t)n * TS + (size_t)t * SDIM + s);
            P[s * PROW + n] = v.x;
            P[(s + 1) * PROW + n] = v.y;
            P[(s + 2) * PROW + n] = v.z;
            P[(s + 3) * PROW + n] = v.w;
        }
    }
    __syncthreads();

    do_proj<false>(P, WTp, nullptr, kw1_pre, kw2_pre, kdd_pre, len, warp, lane);
    __syncthreads();

    // Softmax (lane = head, 32 warps split s; exp left unnormalized)
    {
        float mx = -CUDART_INF_F;
        for (int s = warp; s < len; s += 32) mx = fmaxf(mx, P[s * PROW + lane]);
        red[warp * 33 + lane] = mx;
        __syncthreads();
        if (tid < 32) {
            float m = red[tid];
#pragma unroll
            for (int w = 1; w < 32; w++) m = fmaxf(m, red[w * 33 + tid]);
            gmax[tid] = m;
        }
        __syncthreads();
        float gm = gmax[lane];
        float Z = 0.f;
        for (int s = warp; s < len; s += 32) {
            float e = __expf(P[s * PROW + lane] - gm);
            P[s * PROW + lane] = e;
            Z += e;
        }
        red[warp * 33 + lane] = Z;
        __syncthreads();
        if (tid < 32) {
            float z = 0.f;
#pragma unroll
            for (int w = 0; w < 32; w++) z += red[w * 33 + tid];
            ginv[tid] = 1.0f / z;
        }
        __syncthreads();
    }

    do_proj<true>(P, WTo, ginv, kw1_post, kw2_post, kdd_post, len, warp, lane);
    __syncthreads();

    // Phase E: P[s][n] -> g_B[n][t][s], zero-fill to 128 boundary
    for (int idx = tid; idx < 32 * 256; idx += MID_THREADS) {
        int n = idx >> 8;
        int s = (idx & 255) * 4;
        if (s < pad) {
            float4 v;
            v.x = (s     < len) ? P[s * PROW + n] : 0.f;
            v.y = (s + 1 < len) ? P[(s + 1) * PROW + n] : 0.f;
            v.z = (s + 2 < len) ? P[(s + 2) * PROW + n] : 0.f;
            v.w = (s + 3 < len) ? P[(s + 3) * PROW + n] : 0.f;
            *(float4*)(g_B + (size_t)n * TS + (size_t)t * SDIM + s) = v;
        }
    }
}

// ---------------------------------------------------------------------------
// K3: AV tf32 GEMM. t-tile 64 x d 128, s-chunks of 64, causal bound.
// ---------------------------------------------------------------------------
#define PS_STR 68
#define VS_STR 136
#define AV_SMEM_BYTES ((64 * PS_STR + 64 * VS_STR) * 4)

__global__ __launch_bounds__(256) void av_gemm(const float* __restrict__ V,
                                               float* __restrict__ out) {
    int tt = 15 - blockIdx.x;  // longest first
    int n  = blockIdx.y;

    extern __shared__ uint32_t sm_av[];
    uint32_t* Ps = sm_av;                // [64][68]
    uint32_t* Vs = sm_av + 64 * PS_STR;  // [64][136]

    const float* Pn = g_B + (size_t)n * TS + (size_t)tt * 64 * SDIM;
    const float* Vn = V + (size_t)n * SDIM * DDIM;

    int tid = threadIdx.x;
    int lane = tid & 31, warp = tid >> 5;
    int wm = warp >> 2, wn = warp & 3;
    int g = lane >> 2, tg = lane & 3;

    float acc[2][4][4] = {};
    int nchunks = tt + 1;
    for (int c = 0; c < nchunks; c++) {
        int s0 = c * 64;
        // stage P 64x64
#pragma unroll
        for (int i = 0; i < 4; i++) {
            int idx = tid + i * 256;
            int r = idx >> 4, c4 = idx & 15;
            float4 p = *(const float4*)(Pn + (size_t)r * SDIM + s0 + c4 * 4);
            uint32_t* pd = Ps + r * PS_STR + c4 * 4;
            pd[0] = f2tf32(p.x); pd[1] = f2tf32(p.y); pd[2] = f2tf32(p.z); pd[3] = f2tf32(p.w);
        }
        // stage V 64x128
#pragma unroll
        for (int i = 0; i < 8; i++) {
            int idx = tid + i * 256;
            int r = idx >> 5, c4 = idx & 31;
            float4 v = *(const float4*)(Vn + (size_t)(s0 + r) * DDIM + c4 * 4);
            uint32_t* vd = Vs + r * VS_STR + c4 * 4;
            vd[0] = f2tf32(v.x); vd[1] = f2tf32(v.y); vd[2] = f2tf32(v.z); vd[3] = f2tf32(v.w);
        }
        __syncthreads();

#pragma unroll
        for (int ks = 0; ks < 64; ks += 8) {
            uint32_t a[2][4], b[4][2];
#pragma unroll
            for (int mi = 0; mi < 2; mi++) {
                int rb = wm * 32 + mi * 16;
                a[mi][0] = Ps[(rb + g) * PS_STR + ks + tg];
                a[mi][1] = Ps[(rb + g + 8) * PS_STR + ks + tg];
                a[mi][2] = Ps[(rb + g) * PS_STR + ks + tg + 4];
                a[mi][3] = Ps[(rb + g + 8) * PS_STR + ks + tg + 4];
            }
#pragma unroll
            for (int ni = 0; ni < 4; ni++) {
                int nb = wn * 32 + ni * 8;
                b[ni][0] = Vs[(ks + tg) * VS_STR + nb + g];
                b[ni][1] = Vs[(ks + tg + 4) * VS_STR + nb + g];
            }
#pragma unroll
            for (int mi = 0; mi < 2; mi++)
#pragma unroll
                for (int ni = 0; ni < 4; ni++) mma_tf32(acc[mi][ni], a[mi], b[ni]);
        }
        __syncthreads();
    }

#pragma unroll
    for (int mi = 0; mi < 2; mi++) {
#pragma unroll
        for (int ni = 0; ni < 4; ni++) {
            int t = tt * 64 + wm * 32 + mi * 16 + g;
            int d = wn * 32 + ni * 8 + 2 * tg;
            *(float2*)(out + ((size_t)n * TDIM + t) * DDIM + d)     = make_float2(acc[mi][ni][0], acc[mi][ni][1]);
            *(float2*)(out + ((size_t)n * TDIM + t + 8) * DDIM + d) = make_float2(acc[mi][ni][2], acc[mi][ni][3]);
        }
    }
}

// ---------------------------------------------------------------------------
// Launch
// ---------------------------------------------------------------------------
extern "C" void kernel_launch(void* const* d_in, const int* in_sizes, int n_in,
                              void* d_out, int out_size) {
    const float* query = (const float*)d_in[0];
    const float* key   = (const float*)d_in[1];
    const float* value = (const float*)d_in[2];
    const float* sw_pre  = (const float*)d_in[4];
    const float* qw1_pre = (const float*)d_in[5];
    const float* qw2_pre = (const float*)d_in[6];
    const float* kw1_pre = (const float*)d_in[7];
    const float* kw2_pre = (const float*)d_in[8];
    const float* qdd_pre = (const float*)d_in[9];
    const float* kdd_pre = (const float*)d_in[10];
    const float* sw_post  = (const float*)d_in[11];
    const float* qw1_post = (const float*)d_in[12];
    const float* qw2_post = (const float*)d_in[13];
    const float* kw1_post = (const float*)d_in[14];
    const float* kw2_post = (const float*)d_in[15];
    const float* qdd_post = (const float*)d_in[16];
    const float* kdd_post = (const float*)d_in[17];
    float* out = (float*)d_out;

    size_t mid_smem = MID_SMEM_FLOATS * sizeof(float);
    cudaFuncSetAttribute(middle_kernel, cudaFuncAttributeMaxDynamicSharedMemorySize, (int)mid_smem);
    cudaFuncSetAttribute(qk_gemm, cudaFuncAttributeMaxDynamicSharedMemorySize, QK_SMEM_BYTES);
    cudaFuncSetAttribute(av_gemm, cudaFuncAttributeMaxDynamicSharedMemorySize, AV_SMEM_BYTES);

    qk_gemm<<<dim3(36, 32), 256, QK_SMEM_BYTES>>>(query, key);
    middle_kernel<<<1024, MID_THREADS, mid_smem>>>(
        sw_pre, qw1_pre, qw2_pre, kw1_pre, kw2_pre, qdd_pre, kdd_pre,
        sw_post, qw1_post, qw2_post, kw1_post, kw2_post, qdd_post, kdd_post);
    av_gemm<<<dim3(16, 32), 256, AV_SMEM_BYTES>>>(value, out);
}